// round 1
// baseline (speedup 1.0000x reference)
#include <cuda_runtime.h>
#include <math.h>

#define B     4
#define DIM   256
#define N     2048
#define HEADS 8
#define DH    64
#define HID   512        // HEADS * DH
#define QK_SCALE 0.125f  // DH^-0.5

// Scratch (device globals -> no allocations)
__device__ float g_qkv[(size_t)B * 3 * HID * N];  // [b, 3*hid, n]
__device__ float g_att[(size_t)B * HID * N];      // [b, hid, n]  (channel = h*64 + d)

// ---------------------------------------------------------------------------
// Kernel 1: QKV projection. qkv[b,o,t] = sum_i w[o,i] * x[b,i,t]
// O=1536, I=256, T=2048. Tile 64(o) x 64(t), k-chunk 32.
// ---------------------------------------------------------------------------
__global__ __launch_bounds__(256) void qkv_kernel(const float* __restrict__ x,
                                                  const float* __restrict__ w) {
    __shared__ float wS[64][33];   // [o][k] padded
    __shared__ float xS[32][64];   // [k][t]
    const int t0 = blockIdx.x * 64;
    const int o0 = blockIdx.y * 64;
    const int b  = blockIdx.z;
    const int tid = threadIdx.x;
    const int tx = tid & 15, ty = tid >> 4;

    float acc[4][4] = {};
    const float* xb = x + (size_t)b * DIM * N;

    for (int k0 = 0; k0 < DIM; k0 += 32) {
        #pragma unroll
        for (int u = 0; u < 8; u++) {
            int idx = tid + u * 256;
            wS[idx >> 5][idx & 31] = w[(size_t)(o0 + (idx >> 5)) * DIM + k0 + (idx & 31)];
        }
        #pragma unroll
        for (int u = 0; u < 8; u++) {
            int idx = tid + u * 256;
            xS[idx >> 6][idx & 63] = xb[(size_t)(k0 + (idx >> 6)) * N + t0 + (idx & 63)];
        }
        __syncthreads();
        #pragma unroll
        for (int k = 0; k < 32; k++) {
            float4 bb = *(const float4*)&xS[k][tx * 4];
            float a0 = wS[ty * 4 + 0][k];
            float a1 = wS[ty * 4 + 1][k];
            float a2 = wS[ty * 4 + 2][k];
            float a3 = wS[ty * 4 + 3][k];
            acc[0][0] = fmaf(a0, bb.x, acc[0][0]); acc[0][1] = fmaf(a0, bb.y, acc[0][1]);
            acc[0][2] = fmaf(a0, bb.z, acc[0][2]); acc[0][3] = fmaf(a0, bb.w, acc[0][3]);
            acc[1][0] = fmaf(a1, bb.x, acc[1][0]); acc[1][1] = fmaf(a1, bb.y, acc[1][1]);
            acc[1][2] = fmaf(a1, bb.z, acc[1][2]); acc[1][3] = fmaf(a1, bb.w, acc[1][3]);
            acc[2][0] = fmaf(a2, bb.x, acc[2][0]); acc[2][1] = fmaf(a2, bb.y, acc[2][1]);
            acc[2][2] = fmaf(a2, bb.z, acc[2][2]); acc[2][3] = fmaf(a2, bb.w, acc[2][3]);
            acc[3][0] = fmaf(a3, bb.x, acc[3][0]); acc[3][1] = fmaf(a3, bb.y, acc[3][1]);
            acc[3][2] = fmaf(a3, bb.z, acc[3][2]); acc[3][3] = fmaf(a3, bb.w, acc[3][3]);
        }
        __syncthreads();
    }
    float* ob = g_qkv + (size_t)b * 3 * HID * N;
    #pragma unroll
    for (int r = 0; r < 4; r++) {
        float4 v = make_float4(acc[r][0], acc[r][1], acc[r][2], acc[r][3]);
        *(float4*)&ob[(size_t)(o0 + ty * 4 + r) * N + t0 + tx * 4] = v;
    }
}

// ---------------------------------------------------------------------------
// Kernel 2: flash attention per (b, h, 64-query tile).
// q,k,v layout in g_qkv: [d][t] rows (d stride N).
// ---------------------------------------------------------------------------
__global__ __launch_bounds__(256) void attn_kernel() {
    __shared__ float qS[64][64];   // [d][ii]  (scaled)
    __shared__ float kS[64][32];   // [d][jj]
    __shared__ float vS[64][33];   // [d][jj] padded
    __shared__ float pS[64][34];   // [ii][jj] padded

    const int i0 = blockIdx.x * 64;
    const int h  = blockIdx.y;
    const int b  = blockIdx.z;
    const int tid = threadIdx.x;
    const int tx = tid & 15, ty = tid >> 4;

    const float* qb = g_qkv + ((size_t)b * 3 * HID + h * DH) * N;
    const float* kb = qb + (size_t)HID * N;
    const float* vb = kb + (size_t)HID * N;

    // load q tile (vectorized), pre-scaled
    #pragma unroll
    for (int u = 0; u < 4; u++) {
        int idx = tid + u * 256;          // float4 index; 1024 total
        int d = idx >> 4, ii4 = idx & 15;
        float4 q4 = *(const float4*)&qb[(size_t)d * N + i0 + ii4 * 4];
        q4.x *= QK_SCALE; q4.y *= QK_SCALE; q4.z *= QK_SCALE; q4.w *= QK_SCALE;
        *(float4*)&qS[d][ii4 * 4] = q4;
    }

    float m[4], l[4], o[4][4];
    #pragma unroll
    for (int r = 0; r < 4; r++) {
        m[r] = -1e30f; l[r] = 0.f;
        #pragma unroll
        for (int c = 0; c < 4; c++) o[r][c] = 0.f;
    }

    for (int j0 = 0; j0 < N; j0 += 32) {
        __syncthreads();   // previous tile's pS/vS reads complete (also covers qS on iter 0)
        #pragma unroll
        for (int u = 0; u < 8; u++) {
            int idx = tid + u * 256;
            int d = idx >> 5, jj = idx & 31;
            kS[d][jj] = kb[(size_t)d * N + j0 + jj];
            vS[d][jj] = vb[(size_t)d * N + j0 + jj];
        }
        __syncthreads();

        // scores: s[ii = ty*4+r][jj = tx*2+c]
        float s0[4] = {}, s1[4] = {};
        #pragma unroll
        for (int d = 0; d < 64; d++) {
            float4 qq = *(const float4*)&qS[d][ty * 4];
            float2 kk = *(const float2*)&kS[d][tx * 2];
            s0[0] = fmaf(qq.x, kk.x, s0[0]); s1[0] = fmaf(qq.x, kk.y, s1[0]);
            s0[1] = fmaf(qq.y, kk.x, s0[1]); s1[1] = fmaf(qq.y, kk.y, s1[1]);
            s0[2] = fmaf(qq.z, kk.x, s0[2]); s1[2] = fmaf(qq.z, kk.y, s1[2]);
            s0[3] = fmaf(qq.w, kk.x, s0[3]); s1[3] = fmaf(qq.w, kk.y, s1[3]);
        }

        // online softmax per query row (16-lane reductions share a ty)
        #pragma unroll
        for (int r = 0; r < 4; r++) {
            float tmax = fmaxf(s0[r], s1[r]);
            #pragma unroll
            for (int off = 8; off; off >>= 1)
                tmax = fmaxf(tmax, __shfl_xor_sync(0xffffffffu, tmax, off));
            float mnew  = fmaxf(m[r], tmax);
            float alpha = __expf(m[r] - mnew);
            float p0 = __expf(s0[r] - mnew);
            float p1 = __expf(s1[r] - mnew);
            float rs = p0 + p1;
            #pragma unroll
            for (int off = 8; off; off >>= 1)
                rs += __shfl_xor_sync(0xffffffffu, rs, off);
            l[r] = l[r] * alpha + rs;
            m[r] = mnew;
            #pragma unroll
            for (int c = 0; c < 4; c++) o[r][c] *= alpha;
            pS[ty * 4 + r][tx * 2 + 0] = p0;
            pS[ty * 4 + r][tx * 2 + 1] = p1;
        }
        __syncthreads();

        // o[ii][d = tx*4+c] += sum_jj p[ii][jj] * v[d][jj]
        #pragma unroll
        for (int jj = 0; jj < 32; jj++) {
            float v0 = vS[tx * 4 + 0][jj];
            float v1 = vS[tx * 4 + 1][jj];
            float v2 = vS[tx * 4 + 2][jj];
            float v3 = vS[tx * 4 + 3][jj];
            #pragma unroll
            for (int r = 0; r < 4; r++) {
                float p = pS[ty * 4 + r][jj];
                o[r][0] = fmaf(p, v0, o[r][0]);
                o[r][1] = fmaf(p, v1, o[r][1]);
                o[r][2] = fmaf(p, v2, o[r][2]);
                o[r][3] = fmaf(p, v3, o[r][3]);
            }
        }
    }

    // write: g_att[b, h*64 + d, i] = o[ii][d] / l
    float* ob = g_att + ((size_t)b * HID + h * DH) * N + i0;
    #pragma unroll
    for (int r = 0; r < 4; r++) {
        float inv = 1.f / l[r];
        #pragma unroll
        for (int c = 0; c < 4; c++)
            ob[(size_t)(tx * 4 + c) * N + ty * 4 + r] = o[r][c] * inv;
    }
}

// ---------------------------------------------------------------------------
// Kernel 3: output projection. out[b,o,t] = sum_c w[o,c]*att[b,c,t] + bias[o]
// O=256, C=512, T=2048.
// ---------------------------------------------------------------------------
__global__ __launch_bounds__(256) void proj_kernel(const float* __restrict__ w,
                                                   const float* __restrict__ bias,
                                                   float* __restrict__ out) {
    __shared__ float wS[64][33];
    __shared__ float aS[32][64];
    const int t0 = blockIdx.x * 64;
    const int o0 = blockIdx.y * 64;
    const int b  = blockIdx.z;
    const int tid = threadIdx.x;
    const int tx = tid & 15, ty = tid >> 4;

    float acc[4][4] = {};
    const float* ab = g_att + (size_t)b * HID * N;

    for (int k0 = 0; k0 < HID; k0 += 32) {
        #pragma unroll
        for (int u = 0; u < 8; u++) {
            int idx = tid + u * 256;
            wS[idx >> 5][idx & 31] = w[(size_t)(o0 + (idx >> 5)) * HID + k0 + (idx & 31)];
        }
        #pragma unroll
        for (int u = 0; u < 8; u++) {
            int idx = tid + u * 256;
            aS[idx >> 6][idx & 63] = ab[(size_t)(k0 + (idx >> 6)) * N + t0 + (idx & 63)];
        }
        __syncthreads();
        #pragma unroll
        for (int k = 0; k < 32; k++) {
            float4 bb = *(const float4*)&aS[k][tx * 4];
            float a0 = wS[ty * 4 + 0][k];
            float a1 = wS[ty * 4 + 1][k];
            float a2 = wS[ty * 4 + 2][k];
            float a3 = wS[ty * 4 + 3][k];
            acc[0][0] = fmaf(a0, bb.x, acc[0][0]); acc[0][1] = fmaf(a0, bb.y, acc[0][1]);
            acc[0][2] = fmaf(a0, bb.z, acc[0][2]); acc[0][3] = fmaf(a0, bb.w, acc[0][3]);
            acc[1][0] = fmaf(a1, bb.x, acc[1][0]); acc[1][1] = fmaf(a1, bb.y, acc[1][1]);
            acc[1][2] = fmaf(a1, bb.z, acc[1][2]); acc[1][3] = fmaf(a1, bb.w, acc[1][3]);
            acc[2][0] = fmaf(a2, bb.x, acc[2][0]); acc[2][1] = fmaf(a2, bb.y, acc[2][1]);
            acc[2][2] = fmaf(a2, bb.z, acc[2][2]); acc[2][3] = fmaf(a2, bb.w, acc[2][3]);
            acc[3][0] = fmaf(a3, bb.x, acc[3][0]); acc[3][1] = fmaf(a3, bb.y, acc[3][1]);
            acc[3][2] = fmaf(a3, bb.z, acc[3][2]); acc[3][3] = fmaf(a3, bb.w, acc[3][3]);
        }
        __syncthreads();
    }
    float* ob = out + (size_t)b * DIM * N;
    #pragma unroll
    for (int r = 0; r < 4; r++) {
        float bo = bias[o0 + ty * 4 + r];
        float4 v = make_float4(acc[r][0] + bo, acc[r][1] + bo,
                               acc[r][2] + bo, acc[r][3] + bo);
        *(float4*)&ob[(size_t)(o0 + ty * 4 + r) * N + t0 + tx * 4] = v;
    }
}

// ---------------------------------------------------------------------------
extern "C" void kernel_launch(void* const* d_in, const int* in_sizes, int n_in,
                              void* d_out, int out_size) {
    const float* x     = (const float*)d_in[0];  // [4, 256, 2048]
    const float* w_qkv = (const float*)d_in[1];  // [1536, 256]
    const float* w_out = (const float*)d_in[2];  // [256, 512]
    const float* b_out = (const float*)d_in[3];  // [256]
    float* out = (float*)d_out;                  // [4, 256, 2048]

    qkv_kernel<<<dim3(N / 64, 3 * HID / 64, B), 256>>>(x, w_qkv);
    attn_kernel<<<dim3(N / 64, HEADS, B), 256>>>();
    proj_kernel<<<dim3(N / 64, DIM / 64, B), 256>>>(w_out, b_out, out);
}